// round 1
// baseline (speedup 1.0000x reference)
#include <cuda_runtime.h>
#include <math.h>
#include <float.h>
#include <limits.h>

// Problem constants
#define NTOK 4096      // B*S
#define DDIM 768
#define LDIM 256
#define VOC  50265
#define KSEL 4
#define NSPLIT 8
#define SPLIT_SZ 6284  // ceil(VOC/NSPLIT)

// ---------------- scratch (device globals; no allocations) ----------------
__device__ float  g_zi_pre[NTOK * LDIM];      // x@W_in+b (kept for mse2 ref)
__device__ float  g_zi[NTOK * LDIM];          // normalized
__device__ float  g_zc[VOC * LDIM];           // codebook@W_code+b, normalized in place
__device__ float  g_q[NTOK * DDIM];           // quantized
__device__ float  g_pt_val[NTOK * NSPLIT * KSEL];
__device__ int    g_pt_idx[NTOK * NSPLIT * KSEL];
__device__ int    g_idx[NTOK * KSEL];
__device__ int    g_counts[VOC];
__device__ double g_mse1, g_mse2, g_ent;
__device__ int    g_nz;

// ---------------- helpers ----------------
__device__ __forceinline__ bool better(float v, int j, float v2, int j2) {
    return (v > v2) || (v == v2 && j < j2);
}

// insert (v,j) into sorted-descending top-4 (tie: lower index ranks higher)
__device__ __forceinline__ void ins4(float v, int j, float tv[4], int ti[4]) {
    if (!better(v, j, tv[3], ti[3])) return;
    tv[3] = v; ti[3] = j;
#pragma unroll
    for (int k = 3; k > 0; k--) {
        if (better(tv[k], ti[k], tv[k-1], ti[k-1])) {
            float fv = tv[k]; tv[k] = tv[k-1]; tv[k-1] = fv;
            int   fi = ti[k]; ti[k] = ti[k-1]; ti[k-1] = fi;
        }
    }
}

// ---------------- init: zero accumulators + histogram ----------------
__global__ void init_k() {
    int i = blockIdx.x * blockDim.x + threadIdx.x;
    for (int v = i; v < VOC; v += gridDim.x * blockDim.x) g_counts[v] = 0;
    if (i == 0) { g_mse1 = 0.0; g_mse2 = 0.0; g_ent = 0.0; g_nz = 0; }
}

// ---------------- generic GEMM: C[M,256] = A[M,768] @ W[768,256] + bias ----
// MODE 0: write C.  MODE 1: accumulate sum((C - ref)^2) into g_mse2.
template <int MODE>
__global__ void __launch_bounds__(256, 2)
gemm_k(const float* __restrict__ A, const float* __restrict__ W,
       const float* __restrict__ bias, float* __restrict__ C,
       const float* __restrict__ ref, int M)
{
    __shared__ float As[32][68];   // k-major: As[k][m]
    __shared__ float Ws[32][68];   // Ws[k][n]
    const int tid = threadIdx.x;
    const int m0 = blockIdx.x * 64, n0 = blockIdx.y * 64;
    const int tx = tid & 15, ty = tid >> 4;

    float acc[4][4] = {};
    for (int c0 = 0; c0 < DDIM; c0 += 32) {
#pragma unroll
        for (int t = 0; t < 2; t++) {            // A tile -> transposed store
            int li = tid * 2 + t;
            int row = li >> 3, kq = li & 7;
            float4 v = make_float4(0.f, 0.f, 0.f, 0.f);
            if (m0 + row < M)
                v = *(const float4*)&A[(size_t)(m0 + row) * DDIM + c0 + kq * 4];
            As[kq*4+0][row] = v.x; As[kq*4+1][row] = v.y;
            As[kq*4+2][row] = v.z; As[kq*4+3][row] = v.w;
        }
#pragma unroll
        for (int t = 0; t < 2; t++) {            // W tile -> direct store
            int li = tid * 2 + t;
            int r = li >> 4, nq = li & 15;
            float4 v = *(const float4*)&W[(size_t)(c0 + r) * LDIM + n0 + nq * 4];
            *(float4*)&Ws[r][nq * 4] = v;
        }
        __syncthreads();
#pragma unroll
        for (int kk = 0; kk < 32; kk++) {
            float4 a4 = *(float4*)&As[kk][ty * 4];
            float4 b4 = *(float4*)&Ws[kk][tx * 4];
            float av[4] = {a4.x, a4.y, a4.z, a4.w};
            float bv[4] = {b4.x, b4.y, b4.z, b4.w};
#pragma unroll
            for (int i = 0; i < 4; i++)
#pragma unroll
                for (int j = 0; j < 4; j++)
                    acc[i][j] += av[i] * bv[j];
        }
        __syncthreads();
    }

    if (MODE == 0) {
#pragma unroll
        for (int i = 0; i < 4; i++) {
            int row = m0 + ty * 4 + i;
            if (row < M) {
#pragma unroll
                for (int j = 0; j < 4; j++) {
                    int col = n0 + tx * 4 + j;
                    C[(size_t)row * LDIM + col] = acc[i][j] + bias[col];
                }
            }
        }
    } else {
        double s = 0.0;
#pragma unroll
        for (int i = 0; i < 4; i++) {
            int row = m0 + ty * 4 + i;
            if (row < M) {
#pragma unroll
                for (int j = 0; j < 4; j++) {
                    int col = n0 + tx * 4 + j;
                    float cv = acc[i][j] + bias[col];
                    float d  = cv - ref[(size_t)row * LDIM + col];
                    s += (double)d * (double)d;
                }
            }
        }
#pragma unroll
        for (int off = 16; off > 0; off >>= 1)
            s += __shfl_down_sync(0xFFFFFFFFu, s, off);
        if ((tid & 31) == 0) atomicAdd(&g_mse2, s);
    }
}

// ---------------- row L2-normalize: out = in * rsqrt(sum in^2 + 1e-12) -----
__global__ void norm_k(const float* __restrict__ in, float* __restrict__ out, int M)
{
    int w = (blockIdx.x * blockDim.x + threadIdx.x) >> 5;
    int lane = threadIdx.x & 31;
    if (w >= M) return;
    const float* r = in + (size_t)w * LDIM;
    float vals[8];
    float s = 0.f;
#pragma unroll
    for (int i = 0; i < 8; i++) { vals[i] = r[lane + 32 * i]; s += vals[i] * vals[i]; }
#pragma unroll
    for (int off = 16; off > 0; off >>= 1)
        s += __shfl_xor_sync(0xFFFFFFFFu, s, off);
    float t = s + 1e-12f;
    float sc = rsqrtf(t);
    sc = sc * (1.5f - 0.5f * t * sc * sc);   // Newton: ~1 ulp
    float* o = out + (size_t)w * LDIM;
#pragma unroll
    for (int i = 0; i < 8; i++) o[lane + 32 * i] = vals[i] * sc;
}

// ---------------- fused distance + per-split top-4 ------------------------
// grid: (NTOK/64, NSPLIT). Score = dot(zi, zc) (ordering == -d ordering).
__global__ void __launch_bounds__(256, 2)
topk_k(const float* __restrict__ zi, const float* __restrict__ zc,
       float* __restrict__ pval, int* __restrict__ pidx)
{
    __shared__ float As[32][68];   // zi tile, k-major
    __shared__ float Bs[32][68];   // zc tile, k-major
    __shared__ float scs[64][65];  // score tile [token][code]

    const int tid = threadIdx.x;
    const int t0 = blockIdx.x * 64;
    const int split = blockIdx.y;
    const int j0 = split * SPLIT_SZ;
    const int jend = min(VOC, j0 + SPLIT_SZ);
    const int tx = tid & 15, ty = tid >> 4;
    const int tok = tid >> 2, qq = tid & 3;

    float tv[4] = {-FLT_MAX, -FLT_MAX, -FLT_MAX, -FLT_MAX};
    int   ti[4] = {INT_MAX, INT_MAX, INT_MAX, INT_MAX};

    for (int jc = j0; jc < jend; jc += 64) {
        float acc[4][4] = {};
        for (int c0 = 0; c0 < LDIM; c0 += 32) {
#pragma unroll
            for (int t = 0; t < 2; t++) {
                int li = tid * 2 + t;
                int row = li >> 3, kq = li & 7;
                float4 v = *(const float4*)&zi[(size_t)(t0 + row) * LDIM + c0 + kq * 4];
                As[kq*4+0][row] = v.x; As[kq*4+1][row] = v.y;
                As[kq*4+2][row] = v.z; As[kq*4+3][row] = v.w;
            }
#pragma unroll
            for (int t = 0; t < 2; t++) {
                int li = tid * 2 + t;
                int row = li >> 3, kq = li & 7;
                int j = jc + row;
                float4 v = make_float4(0.f, 0.f, 0.f, 0.f);
                if (j < VOC)
                    v = *(const float4*)&zc[(size_t)j * LDIM + c0 + kq * 4];
                Bs[kq*4+0][row] = v.x; Bs[kq*4+1][row] = v.y;
                Bs[kq*4+2][row] = v.z; Bs[kq*4+3][row] = v.w;
            }
            __syncthreads();
#pragma unroll
            for (int kk = 0; kk < 32; kk++) {
                float4 a4 = *(float4*)&As[kk][ty * 4];
                float4 b4 = *(float4*)&Bs[kk][tx * 4];
                float av[4] = {a4.x, a4.y, a4.z, a4.w};
                float bv[4] = {b4.x, b4.y, b4.z, b4.w};
#pragma unroll
                for (int i = 0; i < 4; i++)
#pragma unroll
                    for (int j = 0; j < 4; j++)
                        acc[i][j] += av[i] * bv[j];
            }
            __syncthreads();
        }
        // dump scores to smem
#pragma unroll
        for (int i = 0; i < 4; i++)
#pragma unroll
            for (int j = 0; j < 4; j++)
                scs[ty * 4 + i][tx * 4 + j] = acc[i][j];
        __syncthreads();
        // each token scanned by 4 threads, 16 codes each
#pragma unroll
        for (int s = 0; s < 16; s++) {
            int cl = qq * 16 + s;
            int j = jc + cl;
            if (j < jend) ins4(scs[tok][cl], j, tv, ti);
        }
        __syncthreads();
    }

    // merge the 4 per-thread quarters of each token (reuse scs as scratch)
    float* mv = &scs[0][0];
    int*   mi = ((int*)&scs[0][0]) + 1024;
#pragma unroll
    for (int k = 0; k < 4; k++) {
        mv[tok * 16 + qq * 4 + k] = tv[k];
        mi[tok * 16 + qq * 4 + k] = ti[k];
    }
    __syncthreads();
    if (qq == 0) {
        float bv[4] = {-FLT_MAX, -FLT_MAX, -FLT_MAX, -FLT_MAX};
        int   bi[4] = {INT_MAX, INT_MAX, INT_MAX, INT_MAX};
#pragma unroll
        for (int c = 0; c < 16; c++)
            ins4(mv[tok * 16 + c], mi[tok * 16 + c], bv, bi);
        size_t base = ((size_t)(t0 + tok) * NSPLIT + split) * KSEL;
#pragma unroll
        for (int k = 0; k < 4; k++) { pval[base + k] = bv[k]; pidx[base + k] = bi[k]; }
    }
}

// ---------------- merge splits -> final top-4, histogram -------------------
__global__ void merge_k(const float* __restrict__ pval, const int* __restrict__ pidx)
{
    int t = blockIdx.x * blockDim.x + threadIdx.x;
    if (t >= NTOK) return;
    float bv[4] = {-FLT_MAX, -FLT_MAX, -FLT_MAX, -FLT_MAX};
    int   bi[4] = {INT_MAX, INT_MAX, INT_MAX, INT_MAX};
#pragma unroll
    for (int c = 0; c < NSPLIT * KSEL; c++)
        ins4(pval[(size_t)t * NSPLIT * KSEL + c], pidx[(size_t)t * NSPLIT * KSEL + c], bv, bi);
#pragma unroll
    for (int k = 0; k < 4; k++) {
        g_idx[t * 4 + k] = bi[k];
        atomicAdd(&g_counts[bi[k]], 1);
    }
}

// ---------------- quantize: q = mean of 4 gathered rows; out = x+(q-x) -----
__global__ void quant_k(const float* __restrict__ x, const float* __restrict__ cb,
                        float* __restrict__ out)
{
    int w = (blockIdx.x * blockDim.x + threadIdx.x) >> 5;   // token
    int lane = threadIdx.x & 31;
    if (w >= NTOK) return;
    const float* c0 = cb + (size_t)g_idx[w * 4 + 0] * DDIM;
    const float* c1 = cb + (size_t)g_idx[w * 4 + 1] * DDIM;
    const float* c2 = cb + (size_t)g_idx[w * 4 + 2] * DDIM;
    const float* c3 = cb + (size_t)g_idx[w * 4 + 3] * DDIM;
    double s = 0.0;
    for (int c = lane; c < DDIM; c += 32) {
        float qv = (((c0[c] + c1[c]) + c2[c]) + c3[c]) * 0.25f;
        float xv = x[(size_t)w * DDIM + c];
        float d = qv - xv;
        out[(size_t)w * DDIM + c] = xv + d;     // x + (q - x), matches STE
        g_q[(size_t)w * DDIM + c] = qv;
        s += (double)d * (double)d;
    }
#pragma unroll
    for (int off = 16; off > 0; off >>= 1)
        s += __shfl_down_sync(0xFFFFFFFFu, s, off);
    if (lane == 0) atomicAdd(&g_mse1, s);
}

// ---------------- entropy / usage over histogram ---------------------------
__global__ void ent_k()
{
    int i0 = blockIdx.x * blockDim.x + threadIdx.x;
    double e = 0.0; int nz = 0;
    for (int i = i0; i < VOC; i += gridDim.x * blockDim.x) {
        int c = g_counts[i];
        if (c > 0) {
            float p = (float)c * (1.0f / (NTOK * KSEL));
            e += (double)(p * logf(p + 1e-10f));
            nz++;
        }
    }
#pragma unroll
    for (int off = 16; off > 0; off >>= 1) {
        e  += __shfl_down_sync(0xFFFFFFFFu, e, off);
        nz += __shfl_down_sync(0xFFFFFFFFu, nz, off);
    }
    if ((threadIdx.x & 31) == 0) { atomicAdd(&g_ent, e); atomicAdd(&g_nz, nz); }
}

// ---------------- finalize scalars -----------------------------------------
__global__ void fin_k(float* __restrict__ out3)
{
    float lp = (float)(-g_ent);
    float mse1 = (float)(g_mse1 / ((double)NTOK * DDIM));
    float mse2 = (float)(g_mse2 / ((double)NTOK * LDIM));
    float loss = 1.25f * mse1 + 1.25f * mse2 + 0.1f * lp;
    out3[0] = loss;
    out3[1] = expf(lp);
    out3[2] = (float)g_nz / (float)VOC / (float)KSEL;
}

// ---------------- launch ----------------------------------------------------
static float* sym_f(const void* s) { void* p = nullptr; cudaGetSymbolAddress(&p, s); return (float*)p; }
static int*   sym_i(const void* s) { void* p = nullptr; cudaGetSymbolAddress(&p, s); return (int*)p; }

extern "C" void kernel_launch(void* const* d_in, const int* in_sizes, int n_in,
                              void* d_out, int out_size)
{
    const float* x  = (const float*)d_in[0];
    const float* cb = (const float*)d_in[1];
    const float* Wi = (const float*)d_in[2];
    const float* bi = (const float*)d_in[3];
    const float* Wc = (const float*)d_in[4];
    const float* bc = (const float*)d_in[5];
    float* out = (float*)d_out;

    float* zi_pre = sym_f(g_zi_pre);
    float* zi     = sym_f(g_zi);
    float* zc     = sym_f(g_zc);
    float* q      = sym_f(g_q);
    float* pval   = sym_f(g_pt_val);
    int*   pidx   = sym_i(g_pt_idx);

    init_k<<<64, 256>>>();
    // zi_pre = x @ W_in + b_in ; zi = l2n(zi_pre)
    gemm_k<0><<<dim3(NTOK / 64, LDIM / 64), 256>>>(x, Wi, bi, zi_pre, nullptr, NTOK);
    norm_k<<<NTOK / 8, 256>>>(zi_pre, zi, NTOK);
    // zc = l2n(codebook @ W_code + b_code)
    gemm_k<0><<<dim3((VOC + 63) / 64, LDIM / 64), 256>>>(cb, Wc, bc, zc, nullptr, VOC);
    norm_k<<<(VOC + 7) / 8, 256>>>(zc, zc, VOC);
    // fused distance + top-4
    topk_k<<<dim3(NTOK / 64, NSPLIT), 256>>>(zi, zc, pval, pidx);
    merge_k<<<NTOK / 256, 256>>>(pval, pidx);
    // quantize + STE output + mse1
    quant_k<<<NTOK / 8, 256>>>(x, cb, out);
    // mse2 = sum((q @ W_code + b_code - zi_pre)^2)
    gemm_k<1><<<dim3(NTOK / 64, LDIM / 64), 256>>>(q, Wc, bc, nullptr, zi_pre, NTOK);
    ent_k<<<64, 256>>>();
    fin_k<<<1, 1>>>(out + (size_t)NTOK * DDIM);
}